// round 15
// baseline (speedup 1.0000x reference)
#include <cuda_runtime.h>
#include <cuda_bf16.h>
#include <math.h>
#include <stdint.h>
#include <stddef.h>

// Problem constants
#define BB    64
#define TT    128
#define DIMK  1024
#define NL    4
#define VOCAB 32000
#define NBLK  128          // persistent grid: <= 148 SMs => all co-resident

// ---------------------------------------------------------------------------
// Device-global scratch.
// ---------------------------------------------------------------------------
__device__ float g_X[(TT + 1) * BB * DIMK];          // 33.8 MB activations
__device__ float g_Xtmp[BB * DIMK];
__device__ float g_H[2 * NL * BB * DIMK];
__device__ unsigned int g_bar_count = 0;
__device__ unsigned int g_bar_gen   = 0;
// bf16-split operands for the tensor-core logits GEMM (16B-aligned)
__device__ __align__(256) __nv_bfloat16 g_Xhi[(size_t)BB * TT * DIMK];  // [m=b*TT+t][k]
__device__ __align__(256) __nv_bfloat16 g_Xlo[(size_t)BB * TT * DIMK];
__device__ __align__(256) __nv_bfloat16 g_Whi[(size_t)VOCAB * DIMK];
__device__ __align__(256) __nv_bfloat16 g_Wlo[(size_t)VOCAB * DIMK];

// ---------------------------------------------------------------------------
// Warp-MMA helpers (standard PTX, sm_80+ -> legal under compute_103)
// ---------------------------------------------------------------------------
__device__ __forceinline__ uint32_t smem_to_u32(const void* p) {
    uint32_t a;
    asm("{ .reg .u64 t; cvta.to.shared.u64 t, %1; cvt.u32.u64 %0, t; }"
        : "=r"(a) : "l"(p));
    return a;
}
__device__ __forceinline__ void ldsm_x4(uint32_t* r, uint32_t addr) {
    asm volatile("ldmatrix.sync.aligned.m8n8.x4.shared.b16 {%0,%1,%2,%3}, [%4];"
                 : "=r"(r[0]), "=r"(r[1]), "=r"(r[2]), "=r"(r[3]) : "r"(addr));
}
__device__ __forceinline__ void mma16816(float* c, const uint32_t* a,
                                         const uint32_t* b) {
    asm volatile(
        "mma.sync.aligned.m16n8k16.row.col.f32.bf16.bf16.f32 "
        "{%0,%1,%2,%3}, {%4,%5,%6,%7}, {%8,%9}, {%0,%1,%2,%3};"
        : "+f"(c[0]), "+f"(c[1]), "+f"(c[2]), "+f"(c[3])
        : "r"(a[0]), "r"(a[1]), "r"(a[2]), "r"(a[3]), "r"(b[0]), "r"(b[1]));
}

// ---------------------------------------------------------------------------
// Software grid barrier — EXACT R8 version (atomic polling; proven in
// R8/R11/R12/R14). ld.cg polling is RACY on this chip (R10/R13) — banned.
// ---------------------------------------------------------------------------
__device__ __forceinline__ void grid_bar() {
    __threadfence();
    __syncthreads();
    if (threadIdx.x == 0) {
        unsigned int g = atomicAdd(&g_bar_gen, 0u);
        if (atomicAdd(&g_bar_count, 1u) == NBLK - 1) {
            atomicExch(&g_bar_count, 0u);
            __threadfence();
            atomicExch(&g_bar_gen, g + 1);
        } else {
            while (atomicAdd(&g_bar_gen, 0u) == g) { }
        }
        __threadfence();
    }
    __syncthreads();
}

// ---------------------------------------------------------------------------
// Eigen/XLA fast-tanh (bit-exact, confirmed R8).
// ---------------------------------------------------------------------------
__device__ __forceinline__ float tanh_eigen(float x) {
    const float kClamp = 7.99881172180175781f;
    float xc = fmaxf(fminf(x, kClamp), -kClamp);
    float x2 = __fmul_rn(xc, xc);
    float p;
    p = __fmaf_rn(x2, -2.76076847742355e-16f, 2.00018790482477e-13f);
    p = __fmaf_rn(x2, p, -8.60467152213735e-11f);
    p = __fmaf_rn(x2, p,  5.12229709037114e-08f);
    p = __fmaf_rn(x2, p,  1.48572235717979e-05f);
    p = __fmaf_rn(x2, p,  6.37261928875436e-04f);
    p = __fmaf_rn(x2, p,  4.89352455891786e-03f);
    p = __fmul_rn(xc, p);
    float q;
    q = __fmaf_rn(x2, 1.19825839466702e-06f, 1.18534705686654e-04f);
    q = __fmaf_rn(x2, q, 2.26843463243900e-03f);
    q = __fmaf_rn(x2, q, 4.89352518554385e-03f);
    float r = __fdiv_rn(p, q);
    return (fabsf(x) < 0.0004f) ? x : r;
}

// ---------------------------------------------------------------------------
// RNN sub-stage — 128 threads (proven mapping), UNDER TEST: 64-k chunks
// (was 32). Halves the per-k sync/prefetch/loop overhead. Per-element
// sequential-k FMA chain order is IDENTICAL (k runs 0..1023 in order);
// kc=512 fold now fires every 8 chunks ((q&7)==7 -> k=511/1023), source
// boundary at (q&15)==15 — the exact same element-level arithmetic as the
// bit-exact R8 kernel. Prefetch buffer a[8] is constant-indexed (no spills).
// ---------------------------------------------------------------------------
__device__ __forceinline__ void stage_gemm(
    const float* __restrict__ A1, const float* __restrict__ W1,
    const float* __restrict__ A2, const float* __restrict__ W2,
    const float* __restrict__ b1, const float* __restrict__ b2,
    float* __restrict__ Cout, int nsrc,
    float (*As)[64], float (*Ws)[8], int tid, int n0)
{
    const int n   = tid & 7;             // output column within slice
    const int mq  = tid >> 3;            // 0..15 row quad
    const int lr  = tid >> 1;            // A-load row (0..63)
    const int lk  = (tid & 1) * 32;      // A-load k offset (0 or 32)
    const int wr  = tid >> 3;            // W-load row, valid for tid < 64
    const int wk  = (tid & 7) * 8;       // W-load k offset (0..56)

    float4 a[8];                         // 64 k per chunk: 32 floats/thread
    float4 w0 = make_float4(0.f, 0.f, 0.f, 0.f);
    float4 w1 = make_float4(0.f, 0.f, 0.f, 0.f);

    auto load_chunk = [&](int q) {       // q in [0, nsrc*16)
        const int s  = q >> 4;
        const int kt = (q & 15) * 64;
        const float* A = s ? A2 : A1;
        const float* W = s ? W2 : W1;
        #pragma unroll
        for (int j = 0; j < 8; j++)
            a[j] = __ldcg(reinterpret_cast<const float4*>(
                       A + (size_t)lr * DIMK + kt + lk + j * 4));
        if (tid < 64) {
            w0 = *reinterpret_cast<const float4*>(
                     W + (size_t)(n0 + wr) * DIMK + kt + wk);
            w1 = *reinterpret_cast<const float4*>(
                     W + (size_t)(n0 + wr) * DIMK + kt + wk + 4);
        }
    };

    const int nq = nsrc * 16;            // 16 chunks of 64 k per source
    float T0s[4];
    float T1s[4] = {0.f, 0.f, 0.f, 0.f};
    float tt0 = 0.f, tt1 = 0.f, tt2 = 0.f, tt3 = 0.f;
    float bb0 = 0.f, bb1 = 0.f, bb2 = 0.f, bb3 = 0.f;

    load_chunk(0);
    for (int q = 0; q < nq; q++) {
        __syncthreads();                 // previous chunk fully consumed
        #pragma unroll
        for (int j = 0; j < 8; j++) {
            As[lk + j * 4 + 0][lr] = a[j].x;
            As[lk + j * 4 + 1][lr] = a[j].y;
            As[lk + j * 4 + 2][lr] = a[j].z;
            As[lk + j * 4 + 3][lr] = a[j].w;
        }
        if (tid < 64) {
            Ws[wk + 0][wr] = w0.x;  Ws[wk + 1][wr] = w0.y;
            Ws[wk + 2][wr] = w0.z;  Ws[wk + 3][wr] = w0.w;
            Ws[wk + 4][wr] = w1.x;  Ws[wk + 5][wr] = w1.y;
            Ws[wk + 6][wr] = w1.z;  Ws[wk + 7][wr] = w1.w;
        }
        __syncthreads();
        if (q + 1 < nq) load_chunk(q + 1);       // overlap with compute
        #pragma unroll
        for (int k = 0; k < 64; k++) {
            float  wv = Ws[k][n];
            float4 av = *reinterpret_cast<const float4*>(&As[k][mq * 4]);
            bb0 = __fmaf_rn(av.x, wv, bb0);
            bb1 = __fmaf_rn(av.y, wv, bb1);
            bb2 = __fmaf_rn(av.z, wv, bb2);
            bb3 = __fmaf_rn(av.w, wv, bb3);
        }
        if ((q & 7) == 7) {              // Eigen kc=512 fold boundary
            tt0 = __fadd_rn(tt0, bb0); bb0 = 0.f;
            tt1 = __fadd_rn(tt1, bb1); bb1 = 0.f;
            tt2 = __fadd_rn(tt2, bb2); bb2 = 0.f;
            tt3 = __fadd_rn(tt3, bb3); bb3 = 0.f;
            if ((q & 15) == 15) {        // source boundary
                if (q < 16) { T0s[0]=tt0; T0s[1]=tt1; T0s[2]=tt2; T0s[3]=tt3; }
                else        { T1s[0]=tt0; T1s[1]=tt1; T1s[2]=tt2; T1s[3]=tt3; }
                tt0 = tt1 = tt2 = tt3 = 0.f;
            }
        }
    }

    const float bv1 = b1[n0 + n];
    const float bv2 = (nsrc == 2) ? b2[n0 + n] : 0.f;
    const int m0 = mq * 4;
    #pragma unroll
    for (int j = 0; j < 4; j++) {
        float t0 = (j == 0) ? T0s[0] : (j == 1) ? T0s[1] : (j == 2) ? T0s[2] : T0s[3];
        float t1 = (j == 0) ? T1s[0] : (j == 1) ? T1s[1] : (j == 2) ? T1s[2] : T1s[3];
        float z;
        if (nsrc == 2)
            z = __fadd_rn(__fadd_rn(__fadd_rn(t0, bv1), t1), bv2);
        else
            z = __fadd_rn(t0, bv1);
        __stcg(&Cout[(size_t)(m0 + j) * DIMK + n0 + n], tanh_eigen(z));
    }
}

// ---------------------------------------------------------------------------
// Persistent RNN — 128 threads (proven structure), 64-k chunk smem.
// ---------------------------------------------------------------------------
__global__ __launch_bounds__(128) void rnn_persistent(
    const int*   __restrict__ ids,   const float* __restrict__ wte,
    const float* __restrict__ wxh_w, const float* __restrict__ wxh_b,
    const float* __restrict__ whh_w, const float* __restrict__ whh_b,
    const float* __restrict__ who_w, const float* __restrict__ who_b)
{
    __shared__ __align__(16) float As[64][64];   // 16 KB
    __shared__ float Ws[64][8];                  // 2 KB

    const int tid  = threadIdx.x;
    const int n0   = blockIdx.x * 8;
    const int base = blockIdx.x * 128 + tid;

    for (int i = base; i < NL * BB * DIMK; i += NBLK * 128)
        __stcg(&g_H[i], 0.0f);
    for (int i = base; i < BB * DIMK; i += NBLK * 128) {
        int b = i >> 10, d = i & (DIMK - 1);
        __stcg(&g_X[i], wte[(size_t)ids[b * TT] * DIMK + d]);
    }
    grid_bar();

    const size_t LBD = (size_t)BB * DIMK;
    const size_t WSZ = (size_t)DIMK * DIMK;

    for (int t = 0; t < TT; t++) {
        const int p = t & 1;
        float* Hin  = g_H + (size_t)p       * NL * LBD;
        float* Hout = g_H + (size_t)(1 - p) * NL * LBD;
        const float* xstep = g_X + (size_t)t * LBD;

        for (int l = 0; l < NL; l++) {
            const float* xl = (l == 0) ? xstep : g_Xtmp;
            float* xo = (l == NL - 1) ? (g_X + (size_t)(t + 1) * LBD) : g_Xtmp;

            stage_gemm(Hin + (size_t)l * LBD, whh_w + (size_t)l * WSZ,
                       xl,                    wxh_w + (size_t)l * WSZ,
                       whh_b + (size_t)l * DIMK, wxh_b + (size_t)l * DIMK,
                       Hout + (size_t)l * LBD, 2, As, Ws, tid, n0);
            grid_bar();

            stage_gemm(Hout + (size_t)l * LBD, who_w + (size_t)l * WSZ,
                       nullptr, nullptr,
                       who_b + (size_t)l * DIMK, nullptr,
                       xo, 1, As, Ws, tid, n0);
            grid_bar();
        }
    }
}

// ---------------------------------------------------------------------------
// bf16-split conversion: v = hi + lo.
// ---------------------------------------------------------------------------
__global__ __launch_bounds__(256) void cvt_wte(const float* __restrict__ wte) {
    size_t i = (size_t)blockIdx.x * 256 + threadIdx.x;
    float x = wte[i];
    __nv_bfloat16 h = __float2bfloat16(x);
    g_Whi[i] = h;
    g_Wlo[i] = __float2bfloat16(__fadd_rn(x, -__bfloat162float(h)));
}
__global__ __launch_bounds__(256) void cvt_X() {
    size_t i = (size_t)blockIdx.x * 256 + threadIdx.x;
    int m = (int)(i >> 10);
    int d = (int)(i & (DIMK - 1));
    int b = m >> 7;
    int t = m & (TT - 1);
    float x = g_X[((size_t)(t + 1) * BB + b) * DIMK + d];
    __nv_bfloat16 h = __float2bfloat16(x);
    g_Xhi[i] = h;
    g_Xlo[i] = __float2bfloat16(__fadd_rn(x, -__bfloat162float(h)));
}

// ---------------------------------------------------------------------------
// Tensor-core logits GEMM via mma.sync — PROVEN CORRECT (R11/R12/R14).
// ---------------------------------------------------------------------------
#define LTS  72
#define LTSB (LTS * 2)
#define TILE_BYTES (128 * LTSB)
#define LOG_SMEM   (4 * TILE_BYTES)

__global__ __launch_bounds__(256, 2) void logits_tc(float* __restrict__ out) {
    extern __shared__ __align__(16) char smc[];
    char* sAhi = smc;
    char* sAlo = smc + TILE_BYTES;
    char* sBhi = smc + 2 * TILE_BYTES;
    char* sBlo = smc + 3 * TILE_BYTES;

    const int tid  = threadIdx.x;
    const int lane = tid & 31;
    const int wid  = tid >> 5;
    const int wm   = (wid & 3) * 32;
    const int wn   = (wid >> 2) * 64;
    const int g    = lane >> 2;
    const int tig  = lane & 3;

    const int m0  = blockIdx.x * 128;
    const int n0v = blockIdx.y * 128;

    const int glr = tid >> 1;
    const int glk = (tid & 1) * 32;

    const uint32_t aHiB = smem_to_u32(sAhi), aLoB = smem_to_u32(sAlo);
    const uint32_t bHiB = smem_to_u32(sBhi), bLoB = smem_to_u32(sBlo);
    const int aRow = lane & 15, aCol = (lane >> 4) * 8;
    const int bRow = (lane & 7) + ((lane >> 4) << 3), bCol = ((lane >> 3) & 1) * 8;

    float c[2][8][4];
    #pragma unroll
    for (int i = 0; i < 2; i++)
        #pragma unroll
        for (int j = 0; j < 8; j++)
            #pragma unroll
            for (int q = 0; q < 4; q++) c[i][j][q] = 0.f;

    for (int kt = 0; kt < 16; kt++) {
        const int ks0 = kt * 64;
        __syncthreads();
        {
            const uint4* pAh = (const uint4*)(g_Xhi + (size_t)(m0 + glr) * DIMK + ks0 + glk);
            const uint4* pAl = (const uint4*)(g_Xlo + (size_t)(m0 + glr) * DIMK + ks0 + glk);
            const uint4* pBh = (const uint4*)(g_Whi + (size_t)(n0v + glr) * DIMK + ks0 + glk);
            const uint4* pBl = (const uint4*)(g_Wlo + (size_t)(n0v + glr) * DIMK + ks0 + glk);
            #pragma unroll
            for (int j = 0; j < 4; j++) {
                const int soff = glr * LTSB + (glk + j * 8) * 2;
                *(uint4*)(sAhi + soff) = pAh[j];
                *(uint4*)(sAlo + soff) = pAl[j];
                *(uint4*)(sBhi + soff) = pBh[j];
                *(uint4*)(sBlo + soff) = pBl[j];
            }
        }
        __syncthreads();

        #pragma unroll
        for (int ks = 0; ks < 4; ks++) {
            const int kk = ks * 16;
            uint32_t ah[2][4], al[2][4];
            #pragma unroll
            for (int mf = 0; mf < 2; mf++) {
                const uint32_t ra = (wm + mf * 16 + aRow) * LTSB + (kk + aCol) * 2;
                ldsm_x4(ah[mf], aHiB + ra);
                ldsm_x4(al[mf], aLoB + ra);
            }
            #pragma unroll
            for (int np = 0; np < 4; np++) {
                uint32_t bh[4], bl[4];
                const uint32_t rb = (wn + np * 16 + bRow) * LTSB + (kk + bCol) * 2;
                ldsm_x4(bh, bHiB + rb);
                ldsm_x4(bl, bLoB + rb);
                #pragma unroll
                for (int mf = 0; mf < 2; mf++) {
                    #pragma unroll
                    for (int nf = 0; nf < 2; nf++) {
                        float* cc = c[mf][np * 2 + nf];
                        mma16816(cc, ah[mf], bh + nf * 2);
                        mma16816(cc, ah[mf], bl + nf * 2);
                        mma16816(cc, al[mf], bh + nf * 2);
                    }
                }
            }
        }
    }

    #pragma unroll
    for (int mf = 0; mf < 2; mf++) {
        const size_t r0 = (size_t)(m0 + wm + mf * 16 + g) * VOCAB;
        const size_t r1 = r0 + (size_t)8 * VOCAB;
        #pragma unroll
        for (int j = 0; j < 8; j++) {
            const int col = n0v + wn + j * 8 + tig * 2;
            *(float2*)(out + r0 + col) = make_float2(c[mf][j][0], c[mf][j][1]);
            *(float2*)(out + r1 + col) = make_float2(c[mf][j][2], c[mf][j][3]);
        }
    }
}

// ---------------------------------------------------------------------------
// Launcher. Input order: ids, wte, wxh_w, wxh_b, whh_w, whh_b, who_w, who_b
// ---------------------------------------------------------------------------
extern "C" void kernel_launch(void* const* d_in, const int* in_sizes, int n_in,
                              void* d_out, int out_size)
{
    const int*   ids   = (const int*)  d_in[0];
    const float* wte   = (const float*)d_in[1];
    const float* wxh_w = (const float*)d_in[2];
    const float* wxh_b = (const float*)d_in[3];
    const float* whh_w = (const float*)d_in[4];
    const float* whh_b = (const float*)d_in[5];
    const float* who_w = (const float*)d_in[6];
    const float* who_b = (const float*)d_in[7];
    float* out = (float*)d_out;
    (void)in_sizes; (void)n_in; (void)out_size;

    cudaFuncSetAttribute(logits_tc,
                         cudaFuncAttributeMaxDynamicSharedMemorySize, LOG_SMEM);

    cvt_wte<<<(VOCAB * DIMK) / 256, 256>>>(wte);
    rnn_persistent<<<NBLK, 128>>>(ids, wte, wxh_w, wxh_b,
                                  whh_w, whh_b, who_w, who_b);
    cvt_X<<<(BB * TT * DIMK) / 256, 256>>>();
    logits_tc<<<dim3(BB * TT / 128, VOCAB / 128), 256, LOG_SMEM>>>(out);
}

// round 16
// speedup vs baseline: 1.2362x; 1.2362x over previous
#include <cuda_runtime.h>
#include <cuda_bf16.h>
#include <math.h>
#include <stdint.h>
#include <stddef.h>

// Problem constants
#define BB    64
#define TT    128
#define DIMK  1024
#define NL    4
#define VOCAB 32000
#define NBLK  128          // persistent grid: <= 148 SMs => all co-resident

// ---------------------------------------------------------------------------
// Device-global scratch.
// ---------------------------------------------------------------------------
__device__ float g_X[(TT + 1) * BB * DIMK];          // 33.8 MB activations
__device__ float g_Xtmp[BB * DIMK];
__device__ float g_H[2 * NL * BB * DIMK];
__device__ unsigned int g_bar_count = 0;
__device__ unsigned int g_bar_gen   = 0;
// bf16-split operands for the tensor-core logits GEMM (16B-aligned)
__device__ __align__(256) __nv_bfloat16 g_Xhi[(size_t)BB * TT * DIMK];  // [m=b*TT+t][k]
__device__ __align__(256) __nv_bfloat16 g_Xlo[(size_t)BB * TT * DIMK];
__device__ __align__(256) __nv_bfloat16 g_Whi[(size_t)VOCAB * DIMK];
__device__ __align__(256) __nv_bfloat16 g_Wlo[(size_t)VOCAB * DIMK];

// ---------------------------------------------------------------------------
// Warp-MMA helpers (standard PTX, sm_80+ -> legal under compute_103)
// ---------------------------------------------------------------------------
__device__ __forceinline__ uint32_t smem_to_u32(const void* p) {
    uint32_t a;
    asm("{ .reg .u64 t; cvta.to.shared.u64 t, %1; cvt.u32.u64 %0, t; }"
        : "=r"(a) : "l"(p));
    return a;
}
__device__ __forceinline__ void ldsm_x4(uint32_t* r, uint32_t addr) {
    asm volatile("ldmatrix.sync.aligned.m8n8.x4.shared.b16 {%0,%1,%2,%3}, [%4];"
                 : "=r"(r[0]), "=r"(r[1]), "=r"(r[2]), "=r"(r[3]) : "r"(addr));
}
__device__ __forceinline__ void mma16816(float* c, const uint32_t* a,
                                         const uint32_t* b) {
    asm volatile(
        "mma.sync.aligned.m16n8k16.row.col.f32.bf16.bf16.f32 "
        "{%0,%1,%2,%3}, {%4,%5,%6,%7}, {%8,%9}, {%0,%1,%2,%3};"
        : "+f"(c[0]), "+f"(c[1]), "+f"(c[2]), "+f"(c[3])
        : "r"(a[0]), "r"(a[1]), "r"(a[2]), "r"(a[3]), "r"(b[0]), "r"(b[1]));
}

// ---------------------------------------------------------------------------
// Software grid barrier — EXACT R8 version (atomic polling; proven in
// R8/R11/R12/R14/R15). ld.cg polling is RACY on this chip (R10/R13) — banned.
// ---------------------------------------------------------------------------
__device__ __forceinline__ void grid_bar() {
    __threadfence();
    __syncthreads();
    if (threadIdx.x == 0) {
        unsigned int g = atomicAdd(&g_bar_gen, 0u);
        if (atomicAdd(&g_bar_count, 1u) == NBLK - 1) {
            atomicExch(&g_bar_count, 0u);
            __threadfence();
            atomicExch(&g_bar_gen, g + 1);
        } else {
            while (atomicAdd(&g_bar_gen, 0u) == g) { }
        }
        __threadfence();
    }
    __syncthreads();
}

// ---------------------------------------------------------------------------
// Eigen/XLA fast-tanh (bit-exact, confirmed R8).
// ---------------------------------------------------------------------------
__device__ __forceinline__ float tanh_eigen(float x) {
    const float kClamp = 7.99881172180175781f;
    float xc = fmaxf(fminf(x, kClamp), -kClamp);
    float x2 = __fmul_rn(xc, xc);
    float p;
    p = __fmaf_rn(x2, -2.76076847742355e-16f, 2.00018790482477e-13f);
    p = __fmaf_rn(x2, p, -8.60467152213735e-11f);
    p = __fmaf_rn(x2, p,  5.12229709037114e-08f);
    p = __fmaf_rn(x2, p,  1.48572235717979e-05f);
    p = __fmaf_rn(x2, p,  6.37261928875436e-04f);
    p = __fmaf_rn(x2, p,  4.89352455891786e-03f);
    p = __fmul_rn(xc, p);
    float q;
    q = __fmaf_rn(x2, 1.19825839466702e-06f, 1.18534705686654e-04f);
    q = __fmaf_rn(x2, q, 2.26843463243900e-03f);
    q = __fmaf_rn(x2, q, 4.89352518554385e-03f);
    float r = __fdiv_rn(p, q);
    return (fabsf(x) < 0.0004f) ? x : r;
}

// ---------------------------------------------------------------------------
// RNN sub-stage — R8 structure (128 threads, 32-k chunks, bit-exact), with
// DEPTH-2 PREFETCH via statically-named double buffers (aA/wA, aB/wB) and a
// manually 2x-unrolled chunk loop: every register index is compile-time
// constant (the R12 spill trap is impossible). Chunk q's loads are issued 2
// chunk-periods ahead (~800 cyc slack vs ~260 cyc L2 latency), so the
// pre-store __syncthreads never waits on memory.
// kc=512 fold boundaries (q=15,31,47,63) are all ODD q -> fold logic lives
// only in the odd half-iteration. Per-element arithmetic order IDENTICAL.
// ---------------------------------------------------------------------------
__device__ __forceinline__ void stage_gemm(
    const float* __restrict__ A1, const float* __restrict__ W1,
    const float* __restrict__ A2, const float* __restrict__ W2,
    const float* __restrict__ b1, const float* __restrict__ b2,
    float* __restrict__ Cout, int nsrc,
    float (*As)[64], float (*Ws)[8], int tid, int n0)
{
    const int n   = tid & 7;
    const int mq  = tid >> 3;
    const int lr  = tid >> 1;
    const int lk  = (tid & 1) * 16;
    const int wr  = tid >> 3;            // valid for tid < 64
    const int wk  = (tid & 7) * 4;

    const int nq = nsrc * 32;

    float4 aA[4], aB[4];
    float4 wA = make_float4(0.f, 0.f, 0.f, 0.f);
    float4 wB = make_float4(0.f, 0.f, 0.f, 0.f);

    float T0s[4];
    float T1s[4] = {0.f, 0.f, 0.f, 0.f};
    float tt0 = 0.f, tt1 = 0.f, tt2 = 0.f, tt3 = 0.f;
    float bb0 = 0.f, bb1 = 0.f, bb2 = 0.f, bb3 = 0.f;

    // load chunk q into the given buffer (static destinations)
#define LOADQ(ab, wb, q) do {                                                 \
        const int _s  = (q) >> 5;                                             \
        const int _kt = ((q) & 31) * 32;                                      \
        const float* _A = _s ? A2 : A1;                                       \
        const float* _W = _s ? W2 : W1;                                       \
        ab[0] = __ldcg((const float4*)(_A + (size_t)lr * DIMK + _kt + lk));      \
        ab[1] = __ldcg((const float4*)(_A + (size_t)lr * DIMK + _kt + lk + 4));  \
        ab[2] = __ldcg((const float4*)(_A + (size_t)lr * DIMK + _kt + lk + 8));  \
        ab[3] = __ldcg((const float4*)(_A + (size_t)lr * DIMK + _kt + lk + 12)); \
        if (tid < 64)                                                         \
            wb = *(const float4*)(_W + (size_t)(n0 + wr) * DIMK + _kt + wk);  \
    } while (0)

    // store buffer to smem, prefetch q+2 into the SAME buffer, compute chunk
#define HALF(ab, wb, qcur) do {                                               \
        __syncthreads();                                                      \
        As[lk +  0][lr] = ab[0].x; As[lk +  1][lr] = ab[0].y;                 \
        As[lk +  2][lr] = ab[0].z; As[lk +  3][lr] = ab[0].w;                 \
        As[lk +  4][lr] = ab[1].x; As[lk +  5][lr] = ab[1].y;                 \
        As[lk +  6][lr] = ab[1].z; As[lk +  7][lr] = ab[1].w;                 \
        As[lk +  8][lr] = ab[2].x; As[lk +  9][lr] = ab[2].y;                 \
        As[lk + 10][lr] = ab[2].z; As[lk + 11][lr] = ab[2].w;                 \
        As[lk + 12][lr] = ab[3].x; As[lk + 13][lr] = ab[3].y;                 \
        As[lk + 14][lr] = ab[3].z; As[lk + 15][lr] = ab[3].w;                 \
        if (tid < 64) {                                                       \
            Ws[wk + 0][wr] = wb.x;  Ws[wk + 1][wr] = wb.y;                    \
            Ws[wk + 2][wr] = wb.z;  Ws[wk + 3][wr] = wb.w;                    \
        }                                                                     \
        __syncthreads();                                                      \
        if ((qcur) + 2 < nq) LOADQ(ab, wb, (qcur) + 2);                       \
        _Pragma("unroll")                                                     \
        for (int k = 0; k < 32; k++) {                                        \
            float  wv = Ws[k][n];                                             \
            float4 av = *(const float4*)(&As[k][mq * 4]);                     \
            bb0 = __fmaf_rn(av.x, wv, bb0);                                   \
            bb1 = __fmaf_rn(av.y, wv, bb1);                                   \
            bb2 = __fmaf_rn(av.z, wv, bb2);                                   \
            bb3 = __fmaf_rn(av.w, wv, bb3);                                   \
        }                                                                     \
    } while (0)

    LOADQ(aA, wA, 0);
    LOADQ(aB, wB, 1);

    for (int q = 0; q < nq; q += 2) {
        HALF(aA, wA, q);                 // even chunk: never a fold boundary
        HALF(aB, wB, q + 1);             // odd chunk: fold boundaries here
        const int qe = q + 1;
        if ((qe & 15) == 15) {           // Eigen kc=512 fold boundary
            tt0 = __fadd_rn(tt0, bb0); bb0 = 0.f;
            tt1 = __fadd_rn(tt1, bb1); bb1 = 0.f;
            tt2 = __fadd_rn(tt2, bb2); bb2 = 0.f;
            tt3 = __fadd_rn(tt3, bb3); bb3 = 0.f;
            if ((qe & 31) == 31) {       // source boundary
                if (qe < 32) { T0s[0]=tt0; T0s[1]=tt1; T0s[2]=tt2; T0s[3]=tt3; }
                else         { T1s[0]=tt0; T1s[1]=tt1; T1s[2]=tt2; T1s[3]=tt3; }
                tt0 = tt1 = tt2 = tt3 = 0.f;
            }
        }
    }
#undef HALF
#undef LOADQ

    const float bv1 = b1[n0 + n];
    const float bv2 = (nsrc == 2) ? b2[n0 + n] : 0.f;
    const int m0 = mq * 4;
    #pragma unroll
    for (int j = 0; j < 4; j++) {
        float t0 = (j == 0) ? T0s[0] : (j == 1) ? T0s[1] : (j == 2) ? T0s[2] : T0s[3];
        float t1 = (j == 0) ? T1s[0] : (j == 1) ? T1s[1] : (j == 2) ? T1s[2] : T1s[3];
        float z;
        if (nsrc == 2)
            z = __fadd_rn(__fadd_rn(__fadd_rn(t0, bv1), t1), bv2);
        else
            z = __fadd_rn(t0, bv1);
        __stcg(&Cout[(size_t)(m0 + j) * DIMK + n0 + n], tanh_eigen(z));
    }
}

// ---------------------------------------------------------------------------
// Persistent RNN — 128 threads, 32-k chunk smem (proven structure).
// ---------------------------------------------------------------------------
__global__ __launch_bounds__(128) void rnn_persistent(
    const int*   __restrict__ ids,   const float* __restrict__ wte,
    const float* __restrict__ wxh_w, const float* __restrict__ wxh_b,
    const float* __restrict__ whh_w, const float* __restrict__ whh_b,
    const float* __restrict__ who_w, const float* __restrict__ who_b)
{
    __shared__ __align__(16) float As[32][64];
    __shared__ float Ws[32][8];

    const int tid  = threadIdx.x;
    const int n0   = blockIdx.x * 8;
    const int base = blockIdx.x * 128 + tid;

    for (int i = base; i < NL * BB * DIMK; i += NBLK * 128)
        __stcg(&g_H[i], 0.0f);
    for (int i = base; i < BB * DIMK; i += NBLK * 128) {
        int b = i >> 10, d = i & (DIMK - 1);
        __stcg(&g_X[i], wte[(size_t)ids[b * TT] * DIMK + d]);
    }
    grid_bar();

    const size_t LBD = (size_t)BB * DIMK;
    const size_t WSZ = (size_t)DIMK * DIMK;

    for (int t = 0; t < TT; t++) {
        const int p = t & 1;
        float* Hin  = g_H + (size_t)p       * NL * LBD;
        float* Hout = g_H + (size_t)(1 - p) * NL * LBD;
        const float* xstep = g_X + (size_t)t * LBD;

        for (int l = 0; l < NL; l++) {
            const float* xl = (l == 0) ? xstep : g_Xtmp;
            float* xo = (l == NL - 1) ? (g_X + (size_t)(t + 1) * LBD) : g_Xtmp;

            stage_gemm(Hin + (size_t)l * LBD, whh_w + (size_t)l * WSZ,
                       xl,                    wxh_w + (size_t)l * WSZ,
                       whh_b + (size_t)l * DIMK, wxh_b + (size_t)l * DIMK,
                       Hout + (size_t)l * LBD, 2, As, Ws, tid, n0);
            grid_bar();

            stage_gemm(Hout + (size_t)l * LBD, who_w + (size_t)l * WSZ,
                       nullptr, nullptr,
                       who_b + (size_t)l * DIMK, nullptr,
                       xo, 1, As, Ws, tid, n0);
            grid_bar();
        }
    }
}

// ---------------------------------------------------------------------------
// bf16-split conversion: v = hi + lo.
// ---------------------------------------------------------------------------
__global__ __launch_bounds__(256) void cvt_wte(const float* __restrict__ wte) {
    size_t i = (size_t)blockIdx.x * 256 + threadIdx.x;
    float x = wte[i];
    __nv_bfloat16 h = __float2bfloat16(x);
    g_Whi[i] = h;
    g_Wlo[i] = __float2bfloat16(__fadd_rn(x, -__bfloat162float(h)));
}
__global__ __launch_bounds__(256) void cvt_X() {
    size_t i = (size_t)blockIdx.x * 256 + threadIdx.x;
    int m = (int)(i >> 10);
    int d = (int)(i & (DIMK - 1));
    int b = m >> 7;
    int t = m & (TT - 1);
    float x = g_X[((size_t)(t + 1) * BB + b) * DIMK + d];
    __nv_bfloat16 h = __float2bfloat16(x);
    g_Xhi[i] = h;
    g_Xlo[i] = __float2bfloat16(__fadd_rn(x, -__bfloat162float(h)));
}

// ---------------------------------------------------------------------------
// Tensor-core logits GEMM via mma.sync — PROVEN CORRECT (R11/R12/R14/R15).
// ---------------------------------------------------------------------------
#define LTS  72
#define LTSB (LTS * 2)
#define TILE_BYTES (128 * LTSB)
#define LOG_SMEM   (4 * TILE_BYTES)

__global__ __launch_bounds__(256, 2) void logits_tc(float* __restrict__ out) {
    extern __shared__ __align__(16) char smc[];
    char* sAhi = smc;
    char* sAlo = smc + TILE_BYTES;
    char* sBhi = smc + 2 * TILE_BYTES;
    char* sBlo = smc + 3 * TILE_BYTES;

    const int tid  = threadIdx.x;
    const int lane = tid & 31;
    const int wid  = tid >> 5;
    const int wm   = (wid & 3) * 32;
    const int wn   = (wid >> 2) * 64;
    const int g    = lane >> 2;
    const int tig  = lane & 3;

    const int m0  = blockIdx.x * 128;
    const int n0v = blockIdx.y * 128;

    const int glr = tid >> 1;
    const int glk = (tid & 1) * 32;

    const uint32_t aHiB = smem_to_u32(sAhi), aLoB = smem_to_u32(sAlo);
    const uint32_t bHiB = smem_to_u32(sBhi), bLoB = smem_to_u32(sBlo);
    const int aRow = lane & 15, aCol = (lane >> 4) * 8;
    const int bRow = (lane & 7) + ((lane >> 4) << 3), bCol = ((lane >> 3) & 1) * 8;

    float c[2][8][4];
    #pragma unroll
    for (int i = 0; i < 2; i++)
        #pragma unroll
        for (int j = 0; j < 8; j++)
            #pragma unroll
            for (int q = 0; q < 4; q++) c[i][j][q] = 0.f;

    for (int kt = 0; kt < 16; kt++) {
        const int ks0 = kt * 64;
        __syncthreads();
        {
            const uint4* pAh = (const uint4*)(g_Xhi + (size_t)(m0 + glr) * DIMK + ks0 + glk);
            const uint4* pAl = (const uint4*)(g_Xlo + (size_t)(m0 + glr) * DIMK + ks0 + glk);
            const uint4* pBh = (const uint4*)(g_Whi + (size_t)(n0v + glr) * DIMK + ks0 + glk);
            const uint4* pBl = (const uint4*)(g_Wlo + (size_t)(n0v + glr) * DIMK + ks0 + glk);
            #pragma unroll
            for (int j = 0; j < 4; j++) {
                const int soff = glr * LTSB + (glk + j * 8) * 2;
                *(uint4*)(sAhi + soff) = pAh[j];
                *(uint4*)(sAlo + soff) = pAl[j];
                *(uint4*)(sBhi + soff) = pBh[j];
                *(uint4*)(sBlo + soff) = pBl[j];
            }
        }
        __syncthreads();

        #pragma unroll
        for (int ks = 0; ks < 4; ks++) {
            const int kk = ks * 16;
            uint32_t ah[2][4], al[2][4];
            #pragma unroll
            for (int mf = 0; mf < 2; mf++) {
                const uint32_t ra = (wm + mf * 16 + aRow) * LTSB + (kk + aCol) * 2;
                ldsm_x4(ah[mf], aHiB + ra);
                ldsm_x4(al[mf], aLoB + ra);
            }
            #pragma unroll
            for (int np = 0; np < 4; np++) {
                uint32_t bh[4], bl[4];
                const uint32_t rb = (wn + np * 16 + bRow) * LTSB + (kk + bCol) * 2;
                ldsm_x4(bh, bHiB + rb);
                ldsm_x4(bl, bLoB + rb);
                #pragma unroll
                for (int mf = 0; mf < 2; mf++) {
                    #pragma unroll
                    for (int nf = 0; nf < 2; nf++) {
                        float* cc = c[mf][np * 2 + nf];
                        mma16816(cc, ah[mf], bh + nf * 2);
                        mma16816(cc, ah[mf], bl + nf * 2);
                        mma16816(cc, al[mf], bh + nf * 2);
                    }
                }
            }
        }
    }

    #pragma unroll
    for (int mf = 0; mf < 2; mf++) {
        const size_t r0 = (size_t)(m0 + wm + mf * 16 + g) * VOCAB;
        const size_t r1 = r0 + (size_t)8 * VOCAB;
        #pragma unroll
        for (int j = 0; j < 8; j++) {
            const int col = n0v + wn + j * 8 + tig * 2;
            *(float2*)(out + r0 + col) = make_float2(c[mf][j][0], c[mf][j][1]);
            *(float2*)(out + r1 + col) = make_float2(c[mf][j][2], c[mf][j][3]);
        }
    }
}

// ---------------------------------------------------------------------------
// Launcher. Input order: ids, wte, wxh_w, wxh_b, whh_w, whh_b, who_w, who_b
// ---------------------------------------------------------------------------
extern "C" void kernel_launch(void* const* d_in, const int* in_sizes, int n_in,
                              void* d_out, int out_size)
{
    const int*   ids   = (const int*)  d_in[0];
    const float* wte   = (const float*)d_in[1];
    const float* wxh_w = (const float*)d_in[2];
    const float* wxh_b = (const float*)d_in[3];
    const float* whh_w = (const float*)d_in[4];
    const float* whh_b = (const float*)d_in[5];
    const float* who_w = (const float*)d_in[6];
    const float* who_b = (const float*)d_in[7];
    float* out = (float*)d_out;
    (void)in_sizes; (void)n_in; (void)out_size;

    cudaFuncSetAttribute(logits_tc,
                         cudaFuncAttributeMaxDynamicSharedMemorySize, LOG_SMEM);

    cvt_wte<<<(VOCAB * DIMK) / 256, 256>>>(wte);
    rnn_persistent<<<NBLK, 128>>>(ids, wte, wxh_w, wxh_b,
                                  whh_w, whh_b, who_w, who_b);
    cvt_X<<<(BB * TT * DIMK) / 256, 256>>>();
    logits_tc<<<dim3(BB * TT / 128, VOCAB / 128), 256, LOG_SMEM>>>(out);
}